// round 17
// baseline (speedup 1.0000x reference)
#include <cuda_runtime.h>
#include <cuda_bf16.h>
#include <math.h>
#include <stdint.h>

// ---------------- problem constants ----------------
#define NE_    100000
#define NR_    200
#define RDIM_  384
#define BB     8192
#define NCOL   406          // 6 scalar cols + 2*NR
#define GAMMA_F 12.0f
#define KA     512          // Adiff K-region
#define KW     1024         // W (t-histogram) K-region, t in [0,1000) zero-padded
#define KTOT   (KA + KW)    // 1536

#define LOGK (13.287712379549449f / 128.0f)   // log2(10000)/128

// ---------------- scratch (__device__ globals; no allocs allowed) ----------------
__device__ float    g_scabs[BB];                          // per-row sc_abs
__device__ __align__(16) __nv_bfloat16 g_AB[BB * KTOT];   // A: [Adiff | W] per row (24 MB)
__device__ __align__(16) __nv_bfloat16 g_Bm[256 * KTOT];  // B: [Wc ; PosTable] (768 KB)

// ======================================================================
// PTX helpers
// ======================================================================
__device__ __forceinline__ uint32_t smem_u32(const void* p) {
    uint32_t a;
    asm("{ .reg .u64 t; cvta.to.shared.u64 t, %1; cvt.u32.u64 %0, t; }" : "=r"(a) : "l"(p));
    return a;
}
__device__ __forceinline__ void cp_async16(uint32_t dst, const void* src) {
    asm volatile("cp.async.cg.shared.global [%0], [%1], 16;" :: "r"(dst), "l"(src));
}
__device__ __forceinline__ void cp_commit() {
    asm volatile("cp.async.commit_group;");
}
__device__ __forceinline__ void cp_wait0() {
    asm volatile("cp.async.wait_group 0;");
}
__device__ __forceinline__ void ldmatrix_x4(uint32_t* r, uint32_t addr) {
    asm volatile("ldmatrix.sync.aligned.m8n8.x4.shared.b16 {%0,%1,%2,%3}, [%4];"
                 : "=r"(r[0]), "=r"(r[1]), "=r"(r[2]), "=r"(r[3]) : "r"(addr));
}
__device__ __forceinline__ void mma16816(float* c, const uint32_t* a, const uint32_t* b) {
    asm volatile(
        "mma.sync.aligned.m16n8k16.row.col.f32.bf16.bf16.f32 "
        "{%0,%1,%2,%3}, {%4,%5,%6,%7}, {%8,%9}, {%0,%1,%2,%3};"
        : "+f"(c[0]), "+f"(c[1]), "+f"(c[2]), "+f"(c[3])
        : "r"(a[0]), "r"(a[1]), "r"(a[2]), "r"(a[3]), "r"(b[0]), "r"(b[1]));
}

// ======================================================================
// Launch 1: build B operand g_Bm[n][k]  (unchanged)
// ======================================================================
__global__ void __launch_bounds__(512) k_pre(const float* __restrict__ w_e) {
    const int n = blockIdx.x;       // 0..255
    const int tid = threadIdx.x;
    const float f = exp2f(-(float)(n & 127) * LOGK);
    for (int k = tid; k < KTOT; k += 512) {
        float v;
        if (k < KA) {
            if (n < 128) {
                v = w_e[k * 128 + n];
                if (k >= 256) v = -v;
            } else {
                v = w_e[(k ^ 256) * 128 + (n - 128)];
                if (k < 256) v = -v;
            }
        } else if (k < KA + 1000) {
            float t = (float)(k - KA);
            float s, c;
            sincosf(t * f, &s, &c);
            v = (n < 128) ? c : s;
        } else {
            v = 0.0f;
        }
        g_Bm[n * KTOT + k] = __float2bfloat16(v);
    }
}

// ======================================================================
// Launch 2: per row — signed t-histogram W, Adiff, t_emb, sc_abs
// (unchanged)
// ======================================================================
__global__ void __launch_bounds__(256) k_gather(
    const int* __restrict__ x, int xs,
    const float* __restrict__ e_emb,
    const float* __restrict__ r_emb,
    const float* __restrict__ d_frq, const float* __restrict__ d_phi,
    const float* __restrict__ d_amp,
    const float* __restrict__ m_frq, const float* __restrict__ m_phi,
    const float* __restrict__ m_amp,
    const float* __restrict__ w_rp)
{
    __shared__ float Wrow[KW];      // signed histogram over t
    __shared__ float st[256];
    __shared__ float ot[256];
    __shared__ float red8[8];

    const int b   = blockIdx.x;
    const int tid = threadIdx.x;
    const int base = b * NCOL;

    #pragma unroll
    for (int i = 0; i < 4; i++) Wrow[tid + i * 256] = 0.0f;
    __syncthreads();

    const int s_idx = x[(base + 0) * xs];
    const int r_idx = x[(base + 1) * xs];
    const int o_idx = x[(base + 2) * xs];
    const float dv  = (float)x[(base + 3) * xs];
    const float mv  = (float)x[(base + 4) * xs];

    for (int i = tid; i < 400; i += 256) {
        int side = (i >= 200);
        int n    = i - side * 200;
        int t    = x[(base + 6 + i) * xs];
        float w  = w_rp[r_idx * 200 + n];
        atomicAdd(&Wrow[t], side ? -w : w);
    }

    {
        const int j  = tid;
        const int jm = (j < 128) ? j : (j - 128);
        {
            const size_t e = (size_t)s_idx;
            float angd = fmaf(dv, d_frq[e * 256 + j], d_phi[e * 256 + j]);
            float angm = fmaf(mv, m_frq[e * 256 + j], m_phi[e * 256 + j]);
            float ad = d_amp[e * 128 + jm];
            float am = m_amp[e * 128 + jm];
            st[j] = (j < 128) ? (ad * __cosf(angd) + am * __cosf(angm))
                              : (ad * __sinf(angd) + am * __sinf(angm));
        }
        {
            const size_t e = (size_t)o_idx;
            float angd = fmaf(dv, d_frq[e * 256 + j], d_phi[e * 256 + j]);
            float angm = fmaf(mv, m_frq[e * 256 + j], m_phi[e * 256 + j]);
            float ad = d_amp[e * 128 + jm];
            float am = m_amp[e * 128 + jm];
            ot[j] = (j < 128) ? (ad * __cosf(angd) + am * __cosf(angm))
                              : (ad * __sinf(angd) + am * __sinf(angm));
        }
    }
    __syncthreads();

    const size_t sb = (size_t)s_idx * 512;
    const size_t ob = (size_t)o_idx * 512;
    {
        int k = tid * 2;
        float2 es = *reinterpret_cast<const float2*>(e_emb + sb + k);
        float2 eo = *reinterpret_cast<const float2*>(e_emb + ob + k);
        __nv_bfloat162 h = __floats2bfloat162_rn(es.x - eo.x, es.y - eo.y);
        *reinterpret_cast<unsigned*>(&g_AB[(size_t)b * KTOT + k]) =
            *reinterpret_cast<unsigned*>(&h);
    }
    {
        int k = tid * 4;
        __nv_bfloat162 h0 = __floats2bfloat162_rn(Wrow[k], Wrow[k + 1]);
        __nv_bfloat162 h1 = __floats2bfloat162_rn(Wrow[k + 2], Wrow[k + 3]);
        uint2 q;
        q.x = *reinterpret_cast<unsigned*>(&h0);
        q.y = *reinterpret_cast<unsigned*>(&h1);
        *reinterpret_cast<uint2*>(&g_AB[(size_t)b * KTOT + KA + k]) = q;
    }

    const float scale = (float)(3.141592653589793 / sqrt(6.0 / (double)(NR_ + RDIM_)));
    float sum = 0.0f;
    for (int k = tid; k < 384; k += 256) {
        float pr = r_emb[(size_t)r_idx * 384 + k] * scale;
        float sn, cs;
        __sincosf(pr, &sn, &cs);
        float re_s, im_s, re_o, im_o;
        if (k < 256) {
            re_s = e_emb[sb + k];
            im_s = e_emb[sb + 256 + k];
            re_o = e_emb[ob + k];
            im_o = e_emb[ob + 256 + k];
        } else {
            re_s = st[k - 256];  im_s = st[k - 128];
            re_o = ot[k - 256];  im_o = ot[k - 128];
        }
        float re = re_s * cs - im_s * sn - re_o;
        float im = re_s * sn + im_s * cs - im_o;
        sum += sqrtf(re * re + im * im);
    }

    #pragma unroll
    for (int off = 16; off; off >>= 1) sum += __shfl_down_sync(0xffffffffu, sum, off);
    if ((tid & 31) == 0) red8[tid >> 5] = sum;
    __syncthreads();
    if (tid == 0) {
        float t = 0.0f;
        #pragma unroll
        for (int i = 0; i < 8; i++) t += red8[i];
        g_scabs[b] = t;
    }
}

// ======================================================================
// Launch 3: fused GEMM + sc_rel + output.
//   per block: D[64 x 256] = A_stripe @ B^T  (cp.async 2-stage, ldmatrix),
//   then Df in smem -> per-row sqrt-reduce -> out. 128 blocks = 1 wave.
//   BM=64, BN=256, BK=32, 8 warps (2m x 4n), warp tile 32x64.
// ======================================================================
#define PADK 40
#define NIT  (KTOT / 32)                 // 48
#define A_BYTES (64 * PADK * 2)          // 5120 per stage
#define B_BYTES (256 * PADK * 2)         // 20480 per stage
#define BS_BASE (2 * A_BYTES)            // 10240
#define DF_STRIDE 260                    // floats; 64*260*4 = 66560 B epilogue
#define SMEM_GEMM 66560

__global__ void __launch_bounds__(256) k_gemm(float* __restrict__ out) {
    extern __shared__ __align__(16) unsigned char sm[];
    const uint32_t smb = smem_u32(sm);

    const int tid  = threadIdx.x;
    const int wid  = tid >> 5;
    const int lane = tid & 31;
    const int bm = blockIdx.x * 64;
    const int wm = wid & 1;          // m warp (32 rows)
    const int wn = wid >> 1;         // n warp (64 cols)

    // staging: A 64x32 (1 chunk/thr), B 256x32 (4 chunks/thr, rows r,r+64,r+128,r+192)
    const int sr = tid >> 2;         // 0..63
    const int sc = (tid & 3) * 8;    // 0,8,16,24
    const __nv_bfloat16* agp = g_AB + (size_t)(bm + sr) * KTOT + sc;
    const __nv_bfloat16* bgp = g_Bm + (size_t)sr * KTOT + sc;
    const uint32_t aDst = smb + (uint32_t)((sr * PADK + sc) * 2);
    const uint32_t bDst = smb + BS_BASE + (uint32_t)((sr * PADK + sc) * 2);
    const uint32_t bRowStep = (uint32_t)(64 * PADK * 2);   // +64 n-rows in smem
    const size_t   bGStep   = (size_t)64 * KTOT;           // +64 n-rows in gmem

    // fragment-load lane addressing
    const int arow = lane & 15;
    const int acol = (lane >> 4) * 8;
    const int bnrw = ((lane >> 4) * 8) + (lane & 7);
    const int bcol = ((lane >> 3) & 1) * 8;

    float acc[2][8][4];
    #pragma unroll
    for (int i = 0; i < 2; i++)
        #pragma unroll
        for (int j = 0; j < 8; j++)
            #pragma unroll
            for (int e = 0; e < 4; e++) acc[i][j][e] = 0.0f;

    // prologue: stage tile 0 into buffer 0
    cp_async16(aDst, agp);
    #pragma unroll
    for (int q = 0; q < 4; q++)
        cp_async16(bDst + q * bRowStep, bgp + q * bGStep);
    cp_commit();

    for (int it = 0; it < NIT; it++) {
        const int buf = it & 1;
        cp_wait0();
        __syncthreads();

        if (it + 1 < NIT) {
            const int nb = buf ^ 1;
            const int k0 = (it + 1) * 32;
            cp_async16(aDst + nb * A_BYTES, agp + k0);
            #pragma unroll
            for (int q = 0; q < 4; q++)
                cp_async16(bDst + nb * B_BYTES + q * bRowStep, bgp + k0 + q * bGStep);
            cp_commit();
        }

        const uint32_t sAb = smb + buf * A_BYTES;
        const uint32_t sBb = smb + BS_BASE + buf * B_BYTES;

        #pragma unroll
        for (int ks = 0; ks < 32; ks += 16) {
            uint32_t af[2][4];
            #pragma unroll
            for (int i = 0; i < 2; i++) {
                uint32_t addr = sAb + (uint32_t)(((wm * 32 + i * 16 + arow) * PADK
                                                 + ks + acol) * 2);
                ldmatrix_x4(af[i], addr);
            }
            uint32_t bf[8][2];
            #pragma unroll
            for (int jt = 0; jt < 4; jt++) {
                uint32_t q[4];
                uint32_t addr = sBb + (uint32_t)(((wn * 64 + jt * 16 + bnrw) * PADK
                                                 + ks + bcol) * 2);
                ldmatrix_x4(q, addr);
                bf[jt * 2][0] = q[0]; bf[jt * 2][1] = q[1];
                bf[jt * 2 + 1][0] = q[2]; bf[jt * 2 + 1][1] = q[3];
            }
            #pragma unroll
            for (int i = 0; i < 2; i++)
                #pragma unroll
                for (int j = 0; j < 8; j++)
                    mma16816(acc[i][j], af[i], bf[j]);
        }
        __syncthreads();
    }

    // ---- epilogue: acc -> smem Df[64][260], then per-row sqrt-reduce ----
    float* Df = reinterpret_cast<float*>(sm);
    const int gid = lane >> 2;
    const int tig = lane & 3;
    #pragma unroll
    for (int i = 0; i < 2; i++) {
        int row = wm * 32 + i * 16 + gid;
        #pragma unroll
        for (int j = 0; j < 8; j++) {
            int col = wn * 64 + j * 8 + tig * 2;
            *reinterpret_cast<float2*>(&Df[row * DF_STRIDE + col]) =
                make_float2(acc[i][j][0], acc[i][j][1]);
            *reinterpret_cast<float2*>(&Df[(row + 8) * DF_STRIDE + col]) =
                make_float2(acc[i][j][2], acc[i][j][3]);
        }
    }
    __syncthreads();

    // each warp reduces 8 rows
    #pragma unroll
    for (int rr = 0; rr < 8; rr++) {
        const int row = wid * 8 + rr;
        float4 re = *reinterpret_cast<const float4*>(&Df[row * DF_STRIDE + lane * 4]);
        float4 im = *reinterpret_cast<const float4*>(&Df[row * DF_STRIDE + 128 + lane * 4]);
        float v = sqrtf(re.x * re.x + im.x * im.x)
                + sqrtf(re.y * re.y + im.y * im.y)
                + sqrtf(re.z * re.z + im.z * im.z)
                + sqrtf(re.w * re.w + im.w * im.w);
        #pragma unroll
        for (int off = 16; off; off >>= 1) v += __shfl_down_sync(0xffffffffu, v, off);
        if (lane == 0) {
            int grow = bm + row;
            out[grow] = GAMMA_F - (g_scabs[grow] + v);
        }
    }
}

// ======================================================================
// launcher
// ======================================================================
extern "C" void kernel_launch(void* const* d_in, const int* in_sizes, int n_in,
                              void* d_out, int out_size)
{
    const int*   x     = (const int*)  d_in[0];
    const float* e_emb = (const float*)d_in[1];
    const float* r_emb = (const float*)d_in[2];
    const float* d_frq = (const float*)d_in[3];
    const float* d_phi = (const float*)d_in[4];
    const float* d_amp = (const float*)d_in[5];
    const float* m_frq = (const float*)d_in[6];
    const float* m_phi = (const float*)d_in[7];
    const float* m_amp = (const float*)d_in[8];
    const float* w_e   = (const float*)d_in[9];
    const float* w_rp  = (const float*)d_in[10];
    float* out = (float*)d_out;

    // x arrives as int64 reported in int32 words; infer element stride.
    int xs = in_sizes[0] / (BB * NCOL);
    if (xs < 1) xs = 1;

    cudaFuncSetAttribute(k_gemm, cudaFuncAttributeMaxDynamicSharedMemorySize, SMEM_GEMM);

    k_pre<<<256, 512>>>(w_e);
    k_gather<<<BB, 256>>>(x, xs, e_emb, r_emb, d_frq, d_phi, d_amp,
                          m_frq, m_phi, m_amp, w_rp);
    k_gemm<<<128, 256, SMEM_GEMM>>>(out);
}